// round 14
// baseline (speedup 1.0000x reference)
#include <cuda_runtime.h>
#include <cuda_bf16.h>
#include <cstdint>

#define N_NODES 100000
#define N_EDGES 1600000
#define N_FEAT  16
#define HIDDEN  128
#define N_GRAPHS 512
#define HU2 (HIDDEN / 4)          // 32 uint2 (4 bf16) per node row
#define SCAN_B 1024
#define NB ((N_NODES + SCAN_B - 1) / SCAN_B)   // 98
#define TILE_M 128
#define N_TILES ((N_NODES + TILE_M - 1) / TILE_M)  // 782
#define PITCH 272                 // smem row pitch (bytes): conflict-free frag loads
#define SM_GEMM2 (2 * 128 * PITCH)  // 69632 dynamic smem
#define N_CHUNK 4
#define TILES_PER_CHUNK ((N_TILES + N_CHUNK - 1) / N_CHUNK)   // 196
#define NODES_PER_CHUNK (TILES_PER_CHUNK * TILE_M)            // 25088

// ---- scratch ----
__device__ uint4  g_hb[N_NODES * 16];     // layer-1 h*dinv, bf16 (gemm1 out / gather1 in)
__device__ uint4  g_hb2[N_NODES * 16];    // layer-2 h*dinv, bf16 (gemm2 out / gather2 in)
__device__ uint4  g_outb[N_NODES * 16];   // relu(out+b), bf16 (gather out / gemm2 A / pool in)
__device__ uint4  g_xb[N_NODES * 2];      // x as bf16 rows (16 bf16 = 32B per node)
__device__ uint4  g_w2tb[128 * 16];       // W2^T as bf16 [n][k]
__device__ uint4  g_w1tb[128 * 2];        // W1^T as bf16 [n][k], k=16
__device__ float  g_dinv[N_NODES];
__device__ int    g_deg[N_NODES];
__device__ int    g_cursor[N_NODES];
__device__ int    g_row_start[N_NODES + 1];
__device__ int    g_blocksum[NB];
__device__ int    g_csr_src[N_EDGES];

__device__ __forceinline__ int idx_at(const int* __restrict__ p, int i, int is64) {
    return is64 ? p[2 * i] : p[i];
}

// Lane-parallel dtype detect: indices < 2^31, random — if int64, odd words all 0.
__device__ __forceinline__ int detect64(const int* __restrict__ p) {
    int lane = threadIdx.x & 31;
    int z = (p[2 * lane + 1] == 0);
    return __all_sync(0xffffffffu, z);
}

__device__ __forceinline__ uint32_t smem_u32(const void* p) {
    uint32_t a;
    asm("{ .reg .u64 t; cvta.to.shared.u64 t, %1; cvt.u32.u64 %0, t; }" : "=r"(a) : "l"(p));
    return a;
}

// ---------------------------------------------------------------------------
// x (fp32) -> g_xb (bf16). 8 values per thread. No dependencies.
__global__ void xcvt_kernel(const float* __restrict__ x) {
    int t = blockIdx.x * 256 + threadIdx.x;
    if (t >= N_NODES * 2) return;
    float4 lo4 = __ldg((const float4*)x + t * 2);
    float4 hi4 = __ldg((const float4*)x + t * 2 + 1);
    uint4 u;
    asm("cvt.rn.bf16x2.f32 %0, %1, %2;" : "=r"(u.x) : "f"(lo4.y), "f"(lo4.x));
    asm("cvt.rn.bf16x2.f32 %0, %1, %2;" : "=r"(u.y) : "f"(lo4.w), "f"(lo4.z));
    asm("cvt.rn.bf16x2.f32 %0, %1, %2;" : "=r"(u.z) : "f"(hi4.y), "f"(hi4.x));
    asm("cvt.rn.bf16x2.f32 %0, %1, %2;" : "=r"(u.w) : "f"(hi4.w), "f"(hi4.z));
    g_xb[t] = u;
}

// W1 -> w1tb[n][k] bf16 (transposed). 256 threads: n = t>>1, 8-k chunk = t&1.
__global__ void w1cvt_kernel(const float* __restrict__ W1) {
    int t = threadIdx.x;
    if (t >= 256) return;
    int n = t >> 1, ch = t & 1;
    int k0 = ch * 8;
    uint32_t w[4];
#pragma unroll
    for (int j = 0; j < 4; j++) {
        float lo = W1[(k0 + 2 * j) * HIDDEN + n];
        float hi = W1[(k0 + 2 * j + 1) * HIDDEN + n];
        asm("cvt.rn.bf16x2.f32 %0, %1, %2;" : "=r"(w[j]) : "f"(hi), "f"(lo));
    }
    g_w1tb[t] = make_uint4(w[0], w[1], w[2], w[3]);
}

// W2 -> w2tb[n][k] bf16 (transposed)
__global__ void w2cvt_kernel(const float* __restrict__ W2) {
    int t = blockIdx.x * 256 + threadIdx.x;
    if (t >= 128 * 16) return;
    int n = t >> 4, ch = t & 15;
    int k0 = ch * 8;
    uint32_t w[4];
#pragma unroll
    for (int j = 0; j < 4; j++) {
        float lo = W2[(k0 + 2 * j) * HIDDEN + n];
        float hi = W2[(k0 + 2 * j + 1) * HIDDEN + n];
        asm("cvt.rn.bf16x2.f32 %0, %1, %2;" : "=r"(w[j]) : "f"(hi), "f"(lo));
    }
    g_w2tb[t] = make_uint4(w[0], w[1], w[2], w[3]);
}

__global__ void deg_kernel(const int* __restrict__ ei_raw) {
    int is64 = detect64(ei_raw);
    int e = blockIdx.x * blockDim.x + threadIdx.x;
    if (e >= N_EDGES) return;
    const int* dst = ei_raw + (is64 ? 2 * N_EDGES : N_EDGES);
    atomicAdd(&g_deg[idx_at(dst, e, is64)], 1);
}

__global__ void blocksum_kernel() {
    __shared__ int wsum[32];
    int b = blockIdx.x, tid = threadIdx.x;
    int i = b * SCAN_B + tid;
    int v = (i < N_NODES) ? g_deg[i] : 0;
#pragma unroll
    for (int off = 16; off; off >>= 1) v += __shfl_down_sync(0xffffffffu, v, off);
    if ((tid & 31) == 0) wsum[tid >> 5] = v;
    __syncthreads();
    if (tid < 32) {
        int s = (tid < SCAN_B / 32) ? wsum[tid] : 0;
#pragma unroll
        for (int off = 16; off; off >>= 1) s += __shfl_down_sync(0xffffffffu, s, off);
        if (tid == 0) g_blocksum[b] = s;
    }
}

// rowstart: hierarchical shfl scan + inline blocksum prefix + dinv (fused)
__global__ void rowstart_kernel() {
    __shared__ int wsum[32];
    __shared__ int s_pref;
    int b = blockIdx.x, tid = threadIdx.x;
    int lane = tid & 31, wrp = tid >> 5;

    if (tid < 32) {
        int sum = 0;
        for (int j = tid; j < b; j += 32) sum += g_blocksum[j];
#pragma unroll
        for (int off = 16; off; off >>= 1) sum += __shfl_down_sync(0xffffffffu, sum, off);
        if (tid == 0) s_pref = sum;
    }

    int i = b * SCAN_B + tid;
    int v = (i < N_NODES) ? g_deg[i] : 0;
    if (i < N_NODES) g_dinv[i] = rsqrtf((float)v + 1.0f);
    int sv = v;
#pragma unroll
    for (int off = 1; off < 32; off <<= 1) {
        int t = __shfl_up_sync(0xffffffffu, sv, off);
        if (lane >= off) sv += t;
    }
    if (lane == 31) wsum[wrp] = sv;
    __syncthreads();
    if (wrp == 0) {
        int s = wsum[lane];
#pragma unroll
        for (int off = 1; off < 32; off <<= 1) {
            int t = __shfl_up_sync(0xffffffffu, s, off);
            if (lane >= off) s += t;
        }
        wsum[lane] = s;
    }
    __syncthreads();
    int incl = sv + (wrp ? wsum[wrp - 1] : 0);
    int excl = incl - v + s_pref;
    if (i < N_NODES) g_row_start[i] = excl;
    if (i == N_NODES - 1) g_row_start[N_NODES] = excl + v;
}

__global__ void bin_kernel(const int* __restrict__ ei_raw) {
    int is64 = detect64(ei_raw);
    int e = blockIdx.x * blockDim.x + threadIdx.x;
    if (e >= N_EDGES) return;
    const int* src = ei_raw;
    const int* dst = ei_raw + (is64 ? 2 * N_EDGES : N_EDGES);
    int d = idx_at(dst, e, is64);
    int pos = atomicAdd(&g_cursor[d], 1);
    g_csr_src[g_row_start[d] + pos] = idx_at(src, e, is64);
}

// ---------------------------------------------------------------------------
// Layer 1 GEMM via HMMA, zero smem: g_hb = bf16( (x_bf16 @ W1) * dinv ).
__global__ __launch_bounds__(256) void gemm1_hmma_kernel() {
    int tid = threadIdx.x, wid = tid >> 5, lane = tid & 31;
    int row0 = blockIdx.x * TILE_M;
    int r = lane >> 2;
    int kc = (lane & 3) * 4;

    const uint8_t* w1b = (const uint8_t*)g_w1tb;
    uint32_t b0[16], b1[16];
#pragma unroll
    for (int f = 0; f < 16; f++) {
        const uint8_t* p = w1b + (f * 8 + r) * 32 + kc;
        b0[f] = *(const uint32_t*)p;
        b1[f] = *(const uint32_t*)(p + 16);
    }

    int rlo = row0 + wid * 16 + r;
    int rhi = rlo + 8;
    const uint8_t* xb = (const uint8_t*)g_xb;
    bool vlo = rlo < N_NODES, vhi = rhi < N_NODES;
    uint32_t a0 = vlo ? *(const uint32_t*)(xb + rlo * 32 + kc) : 0u;
    uint32_t a2 = vlo ? *(const uint32_t*)(xb + rlo * 32 + kc + 16) : 0u;
    uint32_t a1 = vhi ? *(const uint32_t*)(xb + rhi * 32 + kc) : 0u;
    uint32_t a3 = vhi ? *(const uint32_t*)(xb + rhi * 32 + kc + 16) : 0u;

    float dlo = vlo ? g_dinv[rlo] : 0.f;
    float dhi = vhi ? g_dinv[rhi] : 0.f;
    uint32_t* ghw = (uint32_t*)g_hb;
    int wcol = lane & 3;

#pragma unroll
    for (int f = 0; f < 16; f++) {
        float c0 = 0.f, c1 = 0.f, c2 = 0.f, c3 = 0.f;
        asm volatile(
            "mma.sync.aligned.m16n8k16.row.col.f32.bf16.bf16.f32 "
            "{%0,%1,%2,%3},{%4,%5,%6,%7},{%8,%9},{%0,%1,%2,%3};"
            : "+f"(c0), "+f"(c1), "+f"(c2), "+f"(c3)
            : "r"(a0), "r"(a1), "r"(a2), "r"(a3), "r"(b0[f]), "r"(b1[f]));
        uint32_t plo, phi;
        asm("cvt.rn.bf16x2.f32 %0, %1, %2;" : "=r"(plo) : "f"(c1 * dlo), "f"(c0 * dlo));
        asm("cvt.rn.bf16x2.f32 %0, %1, %2;" : "=r"(phi) : "f"(c3 * dhi), "f"(c2 * dhi));
        if (vlo) ghw[rlo * 64 + f * 4 + wcol] = plo;
        if (vhi) ghw[rhi * 64 + f * 4 + wcol] = phi;
    }
}

// ---------------------------------------------------------------------------
// CSR gather over node range [node0, node1):
//   g_outb = bf16(relu( dinv[d]*(h_pre[d] + Σ_s h_pre[s]) + bias ))
// layer 0 reads g_hb; layer 1 reads g_hb2. (Buffer chosen in-kernel: device
// symbols must not be passed by value from host code.)
__global__ void gather_kernel(const float* __restrict__ bias, int layer,
                              int node0, int node1) {
    const uint4* __restrict__ hb = layer ? g_hb2 : g_hb;
    int w = node0 + ((blockIdx.x * blockDim.x + threadIdx.x) >> 5);
    int lane = threadIdx.x & 31;
    if (w >= node1) return;

    int beg = g_row_start[w];
    int end = g_row_start[w + 1];
    int half = lane >> 4;
    int l16 = lane & 15;

    float a0 = 0.f, a1 = 0.f, a2 = 0.f, a3 = 0.f;
    float a4 = 0.f, a5 = 0.f, a6 = 0.f, a7 = 0.f;

    int i = beg;
    for (; i + 1 < end; i += 2) {
        int s = g_csr_src[i + half];
        uint4 v = hb[s * 16 + l16];
        float2 f0 = __bfloat1622float2(*(__nv_bfloat162*)&v.x);
        float2 f1 = __bfloat1622float2(*(__nv_bfloat162*)&v.y);
        float2 f2 = __bfloat1622float2(*(__nv_bfloat162*)&v.z);
        float2 f3 = __bfloat1622float2(*(__nv_bfloat162*)&v.w);
        a0 += f0.x; a1 += f0.y; a2 += f1.x; a3 += f1.y;
        a4 += f2.x; a5 += f2.y; a6 += f3.x; a7 += f3.y;
    }
    if (i < end && half == 0) {
        int s = g_csr_src[i];
        uint4 v = hb[s * 16 + l16];
        float2 f0 = __bfloat1622float2(*(__nv_bfloat162*)&v.x);
        float2 f1 = __bfloat1622float2(*(__nv_bfloat162*)&v.y);
        float2 f2 = __bfloat1622float2(*(__nv_bfloat162*)&v.z);
        float2 f3 = __bfloat1622float2(*(__nv_bfloat162*)&v.w);
        a0 += f0.x; a1 += f0.y; a2 += f1.x; a3 += f1.y;
        a4 += f2.x; a5 += f2.y; a6 += f3.x; a7 += f3.y;
    }

    a0 += __shfl_xor_sync(0xffffffffu, a0, 16);
    a1 += __shfl_xor_sync(0xffffffffu, a1, 16);
    a2 += __shfl_xor_sync(0xffffffffu, a2, 16);
    a3 += __shfl_xor_sync(0xffffffffu, a3, 16);
    a4 += __shfl_xor_sync(0xffffffffu, a4, 16);
    a5 += __shfl_xor_sync(0xffffffffu, a5, 16);
    a6 += __shfl_xor_sync(0xffffffffu, a6, 16);
    a7 += __shfl_xor_sync(0xffffffffu, a7, 16);

    if (half == 0) {
        uint4 v = hb[w * 16 + l16];
        float2 f0 = __bfloat1622float2(*(__nv_bfloat162*)&v.x);
        float2 f1 = __bfloat1622float2(*(__nv_bfloat162*)&v.y);
        float2 f2 = __bfloat1622float2(*(__nv_bfloat162*)&v.z);
        float2 f3 = __bfloat1622float2(*(__nv_bfloat162*)&v.w);
        a0 += f0.x; a1 += f0.y; a2 += f1.x; a3 += f1.y;
        a4 += f2.x; a5 += f2.y; a6 += f3.x; a7 += f3.y;

        float invd = g_dinv[w];
        float4 b0 = ((const float4*)bias)[l16 * 2];
        float4 b1 = ((const float4*)bias)[l16 * 2 + 1];
        float v0 = fmaxf(a0 * invd + b0.x, 0.f);
        float v1 = fmaxf(a1 * invd + b0.y, 0.f);
        float v2 = fmaxf(a2 * invd + b0.z, 0.f);
        float v3 = fmaxf(a3 * invd + b0.w, 0.f);
        float v4 = fmaxf(a4 * invd + b1.x, 0.f);
        float v5 = fmaxf(a5 * invd + b1.y, 0.f);
        float v6 = fmaxf(a6 * invd + b1.z, 0.f);
        float v7 = fmaxf(a7 * invd + b1.w, 0.f);
        uint4 o;
        asm("cvt.rn.bf16x2.f32 %0, %1, %2;" : "=r"(o.x) : "f"(v1), "f"(v0));
        asm("cvt.rn.bf16x2.f32 %0, %1, %2;" : "=r"(o.y) : "f"(v3), "f"(v2));
        asm("cvt.rn.bf16x2.f32 %0, %1, %2;" : "=r"(o.z) : "f"(v5), "f"(v4));
        asm("cvt.rn.bf16x2.f32 %0, %1, %2;" : "=r"(o.w) : "f"(v7), "f"(v6));
        g_outb[w * 16 + l16] = o;
    }
}

// ---------------------------------------------------------------------------
// Layer 2 GEMM via mma.sync (HMMA): g_hb2 = bf16((g_outb @ W2) * dinv)
// Processes tiles [tile0 + blockIdx.x].
__global__ __launch_bounds__(256) void gemm2_hmma_kernel(int tile0) {
    extern __shared__ __align__(16) uint8_t smem[];
    uint8_t* sA = smem;
    uint8_t* sB = smem + 128 * PITCH;

    int tid = threadIdx.x, wid = tid >> 5, lane = tid & 31;
    int row0 = (tile0 + blockIdx.x) * TILE_M;

    const uint4 zero4 = make_uint4(0, 0, 0, 0);
    for (int g = tid; g < 2048; g += 256) {
        int row = g >> 4, ch = g & 15;
        uint4 va = (row0 + row < N_NODES) ? g_outb[(row0 + row) * 16 + ch] : zero4;
        *(uint4*)(sA + row * PITCH + ch * 16) = va;
        *(uint4*)(sB + row * PITCH + ch * 16) = g_w2tb[g];
    }
    __syncthreads();

    float acc[16][4];
#pragma unroll
    for (int f = 0; f < 16; f++)
#pragma unroll
        for (int j = 0; j < 4; j++) acc[f][j] = 0.f;

    int r = lane >> 2;
    int kc2 = (lane & 3) * 4;
    uint32_t aAddr = smem_u32(sA) + (wid * 16 + r) * PITCH + kc2;
    uint32_t bAddr = smem_u32(sB) + r * PITCH + kc2;

#pragma unroll
    for (int ks = 0; ks < 8; ks++) {
        uint32_t a0, a1, a2, a3;
        uint32_t ka = aAddr + ks * 32;
        asm volatile("ld.shared.b32 %0,[%1];" : "=r"(a0) : "r"(ka));
        asm volatile("ld.shared.b32 %0,[%1];" : "=r"(a1) : "r"(ka + 8 * PITCH));
        asm volatile("ld.shared.b32 %0,[%1];" : "=r"(a2) : "r"(ka + 16));
        asm volatile("ld.shared.b32 %0,[%1];" : "=r"(a3) : "r"(ka + 8 * PITCH + 16));
#pragma unroll
        for (int f = 0; f < 16; f++) {
            uint32_t b0, b1;
            uint32_t kb = bAddr + ks * 32 + f * 8 * PITCH;
            asm volatile("ld.shared.b32 %0,[%1];" : "=r"(b0) : "r"(kb));
            asm volatile("ld.shared.b32 %0,[%1];" : "=r"(b1) : "r"(kb + 16));
            asm volatile(
                "mma.sync.aligned.m16n8k16.row.col.f32.bf16.bf16.f32 "
                "{%0,%1,%2,%3},{%4,%5,%6,%7},{%8,%9},{%0,%1,%2,%3};"
                : "+f"(acc[f][0]), "+f"(acc[f][1]), "+f"(acc[f][2]), "+f"(acc[f][3])
                : "r"(a0), "r"(a1), "r"(a2), "r"(a3), "r"(b0), "r"(b1));
        }
    }

    int rlo = row0 + wid * 16 + r;
    int rhi = rlo + 8;
    float dlo = (rlo < N_NODES) ? g_dinv[rlo] : 0.f;
    float dhi = (rhi < N_NODES) ? g_dinv[rhi] : 0.f;
    uint32_t* ghw = (uint32_t*)g_hb2;
    int wcol = (lane & 3);
#pragma unroll
    for (int f = 0; f < 16; f++) {
        uint32_t plo, phi;
        asm("cvt.rn.bf16x2.f32 %0, %1, %2;" : "=r"(plo)
            : "f"(acc[f][1] * dlo), "f"(acc[f][0] * dlo));
        asm("cvt.rn.bf16x2.f32 %0, %1, %2;" : "=r"(phi)
            : "f"(acc[f][3] * dhi), "f"(acc[f][2] * dhi));
        if (rlo < N_NODES) ghw[rlo * 64 + f * 4 + wcol] = plo;
        if (rhi < N_NODES) ghw[rhi * 64 + f * 4 + wcol] = phi;
    }
}

// ---------------------------------------------------------------------------
// Pool + head fused: block per graph (batch sorted). Input g_outb (bf16).
__global__ void pool_head_kernel(const int* __restrict__ batch_raw,
                                 const int* __restrict__ ei_raw,
                                 const float* __restrict__ Wl,
                                 const float* __restrict__ bl,
                                 float* __restrict__ out) {
    int g = blockIdx.x;
    int tid = threadIdx.x;
    int is64 = detect64(ei_raw);

    int lo = 0, hi = N_NODES;
    while (lo < hi) {
        int mid = (lo + hi) >> 1;
        if (idx_at(batch_raw, mid, is64) < g) lo = mid + 1; else hi = mid;
    }
    int beg = lo;
    hi = N_NODES;
    while (lo < hi) {
        int mid = (lo + hi) >> 1;
        if (idx_at(batch_raw, mid, is64) < g + 1) lo = mid + 1; else hi = mid;
    }
    int end = lo;

    const __nv_bfloat16* outb = (const __nv_bfloat16*)g_outb;
    float acc = 0.f;
    for (int n = beg; n < end; n++)
        acc += __bfloat162float(outb[n * HIDDEN + tid]);

    float v = acc * __ldg(Wl + tid);
    __shared__ float wsum[4];
#pragma unroll
    for (int off = 16; off; off >>= 1) v += __shfl_down_sync(0xffffffffu, v, off);
    if ((tid & 31) == 0) wsum[tid >> 5] = v;
    __syncthreads();
    if (tid == 0) {
        float tot = wsum[0] + wsum[1] + wsum[2] + wsum[3];
        float cnt = fmaxf((float)(end - beg), 1.0f);
        out[g] = tot / cnt + __ldg(bl);
    }
}

// ---------------------------------------------------------------------------
extern "C" void kernel_launch(void* const* d_in, const int* in_sizes, int n_in,
                              void* d_out, int out_size) {
    const float* x = (const float*)d_in[0];
    const int* ei_raw = (const int*)d_in[1];
    const int* batch_raw = (const int*)d_in[2];
    const float* W1 = (const float*)d_in[3];
    const float* b1 = (const float*)d_in[4];
    const float* W2 = (const float*)d_in[5];
    const float* b2 = (const float*)d_in[6];
    const float* Wl = (const float*)d_in[7];
    const float* bl = (const float*)d_in[8];
    float* out = (float*)d_out;

    static cudaStream_t s1 = nullptr;
    static cudaEvent_t evF = nullptr, evR = nullptr, evJ = nullptr, evJ2 = nullptr;
    static cudaEvent_t evC[N_CHUNK];
    if (!s1) {
        cudaStreamCreate(&s1);
        cudaEventCreateWithFlags(&evF, cudaEventDisableTiming);
        cudaEventCreateWithFlags(&evR, cudaEventDisableTiming);
        cudaEventCreateWithFlags(&evJ, cudaEventDisableTiming);
        cudaEventCreateWithFlags(&evJ2, cudaEventDisableTiming);
        for (int c = 0; c < N_CHUNK; c++)
            cudaEventCreateWithFlags(&evC[c], cudaEventDisableTiming);
        cudaFuncSetAttribute(gemm2_hmma_kernel,
                             cudaFuncAttributeMaxDynamicSharedMemorySize, SM_GEMM2);
    }

    void *p_deg = nullptr, *p_cur = nullptr;
    cudaGetSymbolAddress(&p_deg, g_deg);
    cudaGetSymbolAddress(&p_cur, g_cursor);
    cudaMemsetAsync(p_deg, 0, N_NODES * sizeof(int));
    cudaMemsetAsync(p_cur, 0, N_NODES * sizeof(int));

    // Fork: side stream converts weights and x (no deps)
    cudaEventRecord(evF, 0);
    cudaStreamWaitEvent(s1, evF, 0);
    w1cvt_kernel<<<1, 256, 0, s1>>>(W1);
    w2cvt_kernel<<<8, 256, 0, s1>>>(W2);
    xcvt_kernel<<<(N_NODES * 2 + 255) / 256, 256, 0, s1>>>(x);

    // Main: degree -> scan (rowstart also produces dinv)
    deg_kernel<<<(N_EDGES + 255) / 256, 256>>>(ei_raw);
    blocksum_kernel<<<NB, SCAN_B>>>();
    rowstart_kernel<<<NB, SCAN_B>>>();
    cudaEventRecord(evR, 0);

    // Side: gemm1 (needs dinv + xb + w1tb) overlapped with bin on main
    cudaStreamWaitEvent(s1, evR, 0);
    gemm1_hmma_kernel<<<N_TILES, 256, 0, s1>>>();
    cudaEventRecord(evJ, s1);

    bin_kernel<<<(N_EDGES + 255) / 256, 256>>>(ei_raw);

    // Pipelined back half: gather1 chunk c (reads g_hb) on main releases
    // gemm2 chunk c (writes g_hb2 — no aliasing with gather1) on s1.
    cudaStreamWaitEvent(0, evJ, 0);
    for (int c = 0; c < N_CHUNK; c++) {
        int n0 = c * NODES_PER_CHUNK;
        int n1 = (c == N_CHUNK - 1) ? N_NODES : (c + 1) * NODES_PER_CHUNK;
        gather_kernel<<<(n1 - n0 + 7) / 8, 256>>>(b1, 0, n0, n1);
        cudaEventRecord(evC[c], 0);
        cudaStreamWaitEvent(s1, evC[c], 0);
        int t0 = c * TILES_PER_CHUNK;
        int nt = ((c == N_CHUNK - 1) ? N_TILES : (c + 1) * TILES_PER_CHUNK) - t0;
        gemm2_hmma_kernel<<<nt, 256, SM_GEMM2, s1>>>(t0);
    }
    cudaEventRecord(evJ2, s1);
    cudaStreamWaitEvent(0, evJ2, 0);

    gather_kernel<<<(N_NODES + 7) / 8, 256>>>(b2, 1, 0, N_NODES);
    pool_head_kernel<<<N_GRAPHS, 128>>>(batch_raw, ei_raw, Wl, bl, out);
}

// round 15
// speedup vs baseline: 1.0717x; 1.0717x over previous
#include <cuda_runtime.h>
#include <cuda_bf16.h>
#include <cstdint>

#define N_NODES 100000
#define N_EDGES 1600000
#define N_FEAT  16
#define HIDDEN  128
#define N_GRAPHS 512
#define HU2 (HIDDEN / 4)          // 32 uint2 (4 bf16) per node row
#define SCAN_B 1024
#define NB ((N_NODES + SCAN_B - 1) / SCAN_B)   // 98
#define TILE_M 128
#define N_TILES ((N_NODES + TILE_M - 1) / TILE_M)  // 782
#define PITCH 272                 // smem row pitch (bytes): conflict-free frag loads
#define SM_GEMM2 (2 * 128 * PITCH)  // 69632 dynamic smem

// ---- scratch ----
__device__ uint4  g_hb[N_NODES * 16];     // layer-1 h*dinv, bf16 (gemm1 out / gather1 in)
__device__ uint4  g_hb2[N_NODES * 16];    // layer-2 h*dinv, bf16 (gemm2 out / gather2 in)
__device__ uint4  g_outb[N_NODES * 16];   // relu(out+b), bf16 (gather out / gemm2 A / pool in)
__device__ uint4  g_xb[N_NODES * 2];      // x as bf16 rows (16 bf16 = 32B per node)
__device__ uint4  g_w2tb[128 * 16];       // W2^T as bf16 [n][k]
__device__ uint4  g_w1tb[128 * 2];        // W1^T as bf16 [n][k], k=16
__device__ float  g_dinv[N_NODES];
__device__ int    g_deg[N_NODES];
__device__ int    g_cursor[N_NODES];      // seeded with row_start by rowstart_kernel
__device__ int    g_row_start[N_NODES + 1];
__device__ int    g_blocksum[NB];
__device__ int    g_csr_src[N_EDGES];

__device__ __forceinline__ int idx_at(const int* __restrict__ p, int i, int is64) {
    return is64 ? p[2 * i] : p[i];
}

// Lane-parallel dtype detect: indices < 2^31, random — if int64, odd words all 0.
__device__ __forceinline__ int detect64(const int* __restrict__ p) {
    int lane = threadIdx.x & 31;
    int z = (p[2 * lane + 1] == 0);
    return __all_sync(0xffffffffu, z);
}

__device__ __forceinline__ uint32_t smem_u32(const void* p) {
    uint32_t a;
    asm("{ .reg .u64 t; cvta.to.shared.u64 t, %1; cvt.u32.u64 %0, t; }" : "=r"(a) : "l"(p));
    return a;
}

// ---------------------------------------------------------------------------
// x (fp32) -> g_xb (bf16). 8 values per thread. No dependencies.
__global__ void xcvt_kernel(const float* __restrict__ x) {
    int t = blockIdx.x * 256 + threadIdx.x;
    if (t >= N_NODES * 2) return;
    float4 lo4 = __ldg((const float4*)x + t * 2);
    float4 hi4 = __ldg((const float4*)x + t * 2 + 1);
    uint4 u;
    asm("cvt.rn.bf16x2.f32 %0, %1, %2;" : "=r"(u.x) : "f"(lo4.y), "f"(lo4.x));
    asm("cvt.rn.bf16x2.f32 %0, %1, %2;" : "=r"(u.y) : "f"(lo4.w), "f"(lo4.z));
    asm("cvt.rn.bf16x2.f32 %0, %1, %2;" : "=r"(u.z) : "f"(hi4.y), "f"(hi4.x));
    asm("cvt.rn.bf16x2.f32 %0, %1, %2;" : "=r"(u.w) : "f"(hi4.w), "f"(hi4.z));
    g_xb[t] = u;
}

// W1 -> w1tb[n][k] bf16 (transposed). 256 threads: n = t>>1, 8-k chunk = t&1.
__global__ void w1cvt_kernel(const float* __restrict__ W1) {
    int t = threadIdx.x;
    if (t >= 256) return;
    int n = t >> 1, ch = t & 1;
    int k0 = ch * 8;
    uint32_t w[4];
#pragma unroll
    for (int j = 0; j < 4; j++) {
        float lo = W1[(k0 + 2 * j) * HIDDEN + n];
        float hi = W1[(k0 + 2 * j + 1) * HIDDEN + n];
        asm("cvt.rn.bf16x2.f32 %0, %1, %2;" : "=r"(w[j]) : "f"(hi), "f"(lo));
    }
    g_w1tb[t] = make_uint4(w[0], w[1], w[2], w[3]);
}

// W2 -> w2tb[n][k] bf16 (transposed)
__global__ void w2cvt_kernel(const float* __restrict__ W2) {
    int t = blockIdx.x * 256 + threadIdx.x;
    if (t >= 128 * 16) return;
    int n = t >> 4, ch = t & 15;
    int k0 = ch * 8;
    uint32_t w[4];
#pragma unroll
    for (int j = 0; j < 4; j++) {
        float lo = W2[(k0 + 2 * j) * HIDDEN + n];
        float hi = W2[(k0 + 2 * j + 1) * HIDDEN + n];
        asm("cvt.rn.bf16x2.f32 %0, %1, %2;" : "=r"(w[j]) : "f"(hi), "f"(lo));
    }
    g_w2tb[t] = make_uint4(w[0], w[1], w[2], w[3]);
}

__global__ void deg_kernel(const int* __restrict__ ei_raw) {
    int is64 = detect64(ei_raw);
    int e = blockIdx.x * blockDim.x + threadIdx.x;
    if (e >= N_EDGES) return;
    const int* dst = ei_raw + (is64 ? 2 * N_EDGES : N_EDGES);
    atomicAdd(&g_deg[idx_at(dst, e, is64)], 1);
}

__global__ void blocksum_kernel() {
    __shared__ int wsum[32];
    int b = blockIdx.x, tid = threadIdx.x;
    int i = b * SCAN_B + tid;
    int v = (i < N_NODES) ? g_deg[i] : 0;
#pragma unroll
    for (int off = 16; off; off >>= 1) v += __shfl_down_sync(0xffffffffu, v, off);
    if ((tid & 31) == 0) wsum[tid >> 5] = v;
    __syncthreads();
    if (tid < 32) {
        int s = (tid < SCAN_B / 32) ? wsum[tid] : 0;
#pragma unroll
        for (int off = 16; off; off >>= 1) s += __shfl_down_sync(0xffffffffu, s, off);
        if (tid == 0) g_blocksum[b] = s;
    }
}

// rowstart: hierarchical shfl scan + inline blocksum prefix + dinv (fused).
// Also seeds g_cursor = row_start so bin_kernel skips the row_start read.
__global__ void rowstart_kernel() {
    __shared__ int wsum[32];
    __shared__ int s_pref;
    int b = blockIdx.x, tid = threadIdx.x;
    int lane = tid & 31, wrp = tid >> 5;

    if (tid < 32) {
        int sum = 0;
        for (int j = tid; j < b; j += 32) sum += g_blocksum[j];
#pragma unroll
        for (int off = 16; off; off >>= 1) sum += __shfl_down_sync(0xffffffffu, sum, off);
        if (tid == 0) s_pref = sum;
    }

    int i = b * SCAN_B + tid;
    int v = (i < N_NODES) ? g_deg[i] : 0;
    if (i < N_NODES) g_dinv[i] = rsqrtf((float)v + 1.0f);
    int sv = v;
#pragma unroll
    for (int off = 1; off < 32; off <<= 1) {
        int t = __shfl_up_sync(0xffffffffu, sv, off);
        if (lane >= off) sv += t;
    }
    if (lane == 31) wsum[wrp] = sv;
    __syncthreads();
    if (wrp == 0) {
        int s = wsum[lane];
#pragma unroll
        for (int off = 1; off < 32; off <<= 1) {
            int t = __shfl_up_sync(0xffffffffu, s, off);
            if (lane >= off) s += t;
        }
        wsum[lane] = s;
    }
    __syncthreads();
    int incl = sv + (wrp ? wsum[wrp - 1] : 0);
    int excl = incl - v + s_pref;
    if (i < N_NODES) {
        g_row_start[i] = excl;
        g_cursor[i] = excl;            // seed bin cursor
    }
    if (i == N_NODES - 1) g_row_start[N_NODES] = excl + v;
}

// bin: cursor pre-seeded with row_start -> atomicAdd gives the slot directly.
__global__ void bin_kernel(const int* __restrict__ ei_raw) {
    int is64 = detect64(ei_raw);
    int e = blockIdx.x * blockDim.x + threadIdx.x;
    if (e >= N_EDGES) return;
    const int* src = ei_raw;
    const int* dst = ei_raw + (is64 ? 2 * N_EDGES : N_EDGES);
    int d = idx_at(dst, e, is64);
    int pos = atomicAdd(&g_cursor[d], 1);
    g_csr_src[pos] = idx_at(src, e, is64);
}

// ---------------------------------------------------------------------------
// Layer 1 GEMM via HMMA, zero smem: g_hb = bf16( (x_bf16 @ W1) * dinv ).
__global__ __launch_bounds__(256) void gemm1_hmma_kernel() {
    int tid = threadIdx.x, wid = tid >> 5, lane = tid & 31;
    int row0 = blockIdx.x * TILE_M;
    int r = lane >> 2;
    int kc = (lane & 3) * 4;

    const uint8_t* w1b = (const uint8_t*)g_w1tb;
    uint32_t b0[16], b1[16];
#pragma unroll
    for (int f = 0; f < 16; f++) {
        const uint8_t* p = w1b + (f * 8 + r) * 32 + kc;
        b0[f] = *(const uint32_t*)p;
        b1[f] = *(const uint32_t*)(p + 16);
    }

    int rlo = row0 + wid * 16 + r;
    int rhi = rlo + 8;
    const uint8_t* xb = (const uint8_t*)g_xb;
    bool vlo = rlo < N_NODES, vhi = rhi < N_NODES;
    uint32_t a0 = vlo ? *(const uint32_t*)(xb + rlo * 32 + kc) : 0u;
    uint32_t a2 = vlo ? *(const uint32_t*)(xb + rlo * 32 + kc + 16) : 0u;
    uint32_t a1 = vhi ? *(const uint32_t*)(xb + rhi * 32 + kc) : 0u;
    uint32_t a3 = vhi ? *(const uint32_t*)(xb + rhi * 32 + kc + 16) : 0u;

    float dlo = vlo ? g_dinv[rlo] : 0.f;
    float dhi = vhi ? g_dinv[rhi] : 0.f;
    uint32_t* ghw = (uint32_t*)g_hb;
    int wcol = lane & 3;

#pragma unroll
    for (int f = 0; f < 16; f++) {
        float c0 = 0.f, c1 = 0.f, c2 = 0.f, c3 = 0.f;
        asm volatile(
            "mma.sync.aligned.m16n8k16.row.col.f32.bf16.bf16.f32 "
            "{%0,%1,%2,%3},{%4,%5,%6,%7},{%8,%9},{%0,%1,%2,%3};"
            : "+f"(c0), "+f"(c1), "+f"(c2), "+f"(c3)
            : "r"(a0), "r"(a1), "r"(a2), "r"(a3), "r"(b0[f]), "r"(b1[f]));
        uint32_t plo, phi;
        asm("cvt.rn.bf16x2.f32 %0, %1, %2;" : "=r"(plo) : "f"(c1 * dlo), "f"(c0 * dlo));
        asm("cvt.rn.bf16x2.f32 %0, %1, %2;" : "=r"(phi) : "f"(c3 * dhi), "f"(c2 * dhi));
        if (vlo) ghw[rlo * 64 + f * 4 + wcol] = plo;
        if (vhi) ghw[rhi * 64 + f * 4 + wcol] = phi;
    }
}

// ---------------------------------------------------------------------------
// CSR gather: g_outb = bf16(relu( dinv[d]*(h_pre[d] + Σ_s h_pre[s]) + bias ))
// layer 0 reads g_hb; layer 1 reads g_hb2 (selected in-kernel).
__global__ void gather_kernel(const float* __restrict__ bias, int layer) {
    const uint4* __restrict__ hb = layer ? g_hb2 : g_hb;
    int w = (blockIdx.x * blockDim.x + threadIdx.x) >> 5;
    int lane = threadIdx.x & 31;
    if (w >= N_NODES) return;

    int beg = g_row_start[w];
    int end = g_row_start[w + 1];
    int half = lane >> 4;
    int l16 = lane & 15;

    float a0 = 0.f, a1 = 0.f, a2 = 0.f, a3 = 0.f;
    float a4 = 0.f, a5 = 0.f, a6 = 0.f, a7 = 0.f;

    int i = beg;
    for (; i + 1 < end; i += 2) {
        int s = g_csr_src[i + half];
        uint4 v = hb[s * 16 + l16];
        float2 f0 = __bfloat1622float2(*(__nv_bfloat162*)&v.x);
        float2 f1 = __bfloat1622float2(*(__nv_bfloat162*)&v.y);
        float2 f2 = __bfloat1622float2(*(__nv_bfloat162*)&v.z);
        float2 f3 = __bfloat1622float2(*(__nv_bfloat162*)&v.w);
        a0 += f0.x; a1 += f0.y; a2 += f1.x; a3 += f1.y;
        a4 += f2.x; a5 += f2.y; a6 += f3.x; a7 += f3.y;
    }
    if (i < end && half == 0) {
        int s = g_csr_src[i];
        uint4 v = hb[s * 16 + l16];
        float2 f0 = __bfloat1622float2(*(__nv_bfloat162*)&v.x);
        float2 f1 = __bfloat1622float2(*(__nv_bfloat162*)&v.y);
        float2 f2 = __bfloat1622float2(*(__nv_bfloat162*)&v.z);
        float2 f3 = __bfloat1622float2(*(__nv_bfloat162*)&v.w);
        a0 += f0.x; a1 += f0.y; a2 += f1.x; a3 += f1.y;
        a4 += f2.x; a5 += f2.y; a6 += f3.x; a7 += f3.y;
    }

    a0 += __shfl_xor_sync(0xffffffffu, a0, 16);
    a1 += __shfl_xor_sync(0xffffffffu, a1, 16);
    a2 += __shfl_xor_sync(0xffffffffu, a2, 16);
    a3 += __shfl_xor_sync(0xffffffffu, a3, 16);
    a4 += __shfl_xor_sync(0xffffffffu, a4, 16);
    a5 += __shfl_xor_sync(0xffffffffu, a5, 16);
    a6 += __shfl_xor_sync(0xffffffffu, a6, 16);
    a7 += __shfl_xor_sync(0xffffffffu, a7, 16);

    if (half == 0) {
        uint4 v = hb[w * 16 + l16];
        float2 f0 = __bfloat1622float2(*(__nv_bfloat162*)&v.x);
        float2 f1 = __bfloat1622float2(*(__nv_bfloat162*)&v.y);
        float2 f2 = __bfloat1622float2(*(__nv_bfloat162*)&v.z);
        float2 f3 = __bfloat1622float2(*(__nv_bfloat162*)&v.w);
        a0 += f0.x; a1 += f0.y; a2 += f1.x; a3 += f1.y;
        a4 += f2.x; a5 += f2.y; a6 += f3.x; a7 += f3.y;

        float invd = g_dinv[w];
        float4 b0 = ((const float4*)bias)[l16 * 2];
        float4 b1 = ((const float4*)bias)[l16 * 2 + 1];
        float v0 = fmaxf(a0 * invd + b0.x, 0.f);
        float v1 = fmaxf(a1 * invd + b0.y, 0.f);
        float v2 = fmaxf(a2 * invd + b0.z, 0.f);
        float v3 = fmaxf(a3 * invd + b0.w, 0.f);
        float v4 = fmaxf(a4 * invd + b1.x, 0.f);
        float v5 = fmaxf(a5 * invd + b1.y, 0.f);
        float v6 = fmaxf(a6 * invd + b1.z, 0.f);
        float v7 = fmaxf(a7 * invd + b1.w, 0.f);
        uint4 o;
        asm("cvt.rn.bf16x2.f32 %0, %1, %2;" : "=r"(o.x) : "f"(v1), "f"(v0));
        asm("cvt.rn.bf16x2.f32 %0, %1, %2;" : "=r"(o.y) : "f"(v3), "f"(v2));
        asm("cvt.rn.bf16x2.f32 %0, %1, %2;" : "=r"(o.z) : "f"(v5), "f"(v4));
        asm("cvt.rn.bf16x2.f32 %0, %1, %2;" : "=r"(o.w) : "f"(v7), "f"(v6));
        g_outb[w * 16 + l16] = o;
    }
}

// ---------------------------------------------------------------------------
// Layer 2 GEMM via mma.sync (HMMA): g_hb2 = bf16((g_outb @ W2) * dinv)
__global__ __launch_bounds__(256) void gemm2_hmma_kernel() {
    extern __shared__ __align__(16) uint8_t smem[];
    uint8_t* sA = smem;
    uint8_t* sB = smem + 128 * PITCH;

    int tid = threadIdx.x, wid = tid >> 5, lane = tid & 31;
    int row0 = blockIdx.x * TILE_M;

    const uint4 zero4 = make_uint4(0, 0, 0, 0);
    for (int g = tid; g < 2048; g += 256) {
        int row = g >> 4, ch = g & 15;
        uint4 va = (row0 + row < N_NODES) ? g_outb[(row0 + row) * 16 + ch] : zero4;
        *(uint4*)(sA + row * PITCH + ch * 16) = va;
        *(uint4*)(sB + row * PITCH + ch * 16) = g_w2tb[g];
    }
    __syncthreads();

    float acc[16][4];
#pragma unroll
    for (int f = 0; f < 16; f++)
#pragma unroll
        for (int j = 0; j < 4; j++) acc[f][j] = 0.f;

    int r = lane >> 2;
    int kc2 = (lane & 3) * 4;
    uint32_t aAddr = smem_u32(sA) + (wid * 16 + r) * PITCH + kc2;
    uint32_t bAddr = smem_u32(sB) + r * PITCH + kc2;

#pragma unroll
    for (int ks = 0; ks < 8; ks++) {
        uint32_t a0, a1, a2, a3;
        uint32_t ka = aAddr + ks * 32;
        asm volatile("ld.shared.b32 %0,[%1];" : "=r"(a0) : "r"(ka));
        asm volatile("ld.shared.b32 %0,[%1];" : "=r"(a1) : "r"(ka + 8 * PITCH));
        asm volatile("ld.shared.b32 %0,[%1];" : "=r"(a2) : "r"(ka + 16));
        asm volatile("ld.shared.b32 %0,[%1];" : "=r"(a3) : "r"(ka + 8 * PITCH + 16));
#pragma unroll
        for (int f = 0; f < 16; f++) {
            uint32_t b0, b1;
            uint32_t kb = bAddr + ks * 32 + f * 8 * PITCH;
            asm volatile("ld.shared.b32 %0,[%1];" : "=r"(b0) : "r"(kb));
            asm volatile("ld.shared.b32 %0,[%1];" : "=r"(b1) : "r"(kb + 16));
            asm volatile(
                "mma.sync.aligned.m16n8k16.row.col.f32.bf16.bf16.f32 "
                "{%0,%1,%2,%3},{%4,%5,%6,%7},{%8,%9},{%0,%1,%2,%3};"
                : "+f"(acc[f][0]), "+f"(acc[f][1]), "+f"(acc[f][2]), "+f"(acc[f][3])
                : "r"(a0), "r"(a1), "r"(a2), "r"(a3), "r"(b0), "r"(b1));
        }
    }

    int rlo = row0 + wid * 16 + r;
    int rhi = rlo + 8;
    float dlo = (rlo < N_NODES) ? g_dinv[rlo] : 0.f;
    float dhi = (rhi < N_NODES) ? g_dinv[rhi] : 0.f;
    uint32_t* ghw = (uint32_t*)g_hb2;
    int wcol = (lane & 3);
#pragma unroll
    for (int f = 0; f < 16; f++) {
        uint32_t plo, phi;
        asm("cvt.rn.bf16x2.f32 %0, %1, %2;" : "=r"(plo)
            : "f"(acc[f][1] * dlo), "f"(acc[f][0] * dlo));
        asm("cvt.rn.bf16x2.f32 %0, %1, %2;" : "=r"(phi)
            : "f"(acc[f][3] * dhi), "f"(acc[f][2] * dhi));
        if (rlo < N_NODES) ghw[rlo * 64 + f * 4 + wcol] = plo;
        if (rhi < N_NODES) ghw[rhi * 64 + f * 4 + wcol] = phi;
    }
}

// ---------------------------------------------------------------------------
// Pool + head fused: block per graph (batch sorted). Input g_outb (bf16).
__global__ void pool_head_kernel(const int* __restrict__ batch_raw,
                                 const int* __restrict__ ei_raw,
                                 const float* __restrict__ Wl,
                                 const float* __restrict__ bl,
                                 float* __restrict__ out) {
    int g = blockIdx.x;
    int tid = threadIdx.x;
    int is64 = detect64(ei_raw);

    int lo = 0, hi = N_NODES;
    while (lo < hi) {
        int mid = (lo + hi) >> 1;
        if (idx_at(batch_raw, mid, is64) < g) lo = mid + 1; else hi = mid;
    }
    int beg = lo;
    hi = N_NODES;
    while (lo < hi) {
        int mid = (lo + hi) >> 1;
        if (idx_at(batch_raw, mid, is64) < g + 1) lo = mid + 1; else hi = mid;
    }
    int end = lo;

    const __nv_bfloat16* outb = (const __nv_bfloat16*)g_outb;
    float acc = 0.f;
    for (int n = beg; n < end; n++)
        acc += __bfloat162float(outb[n * HIDDEN + tid]);

    float v = acc * __ldg(Wl + tid);
    __shared__ float wsum[4];
#pragma unroll
    for (int off = 16; off; off >>= 1) v += __shfl_down_sync(0xffffffffu, v, off);
    if ((tid & 31) == 0) wsum[tid >> 5] = v;
    __syncthreads();
    if (tid == 0) {
        float tot = wsum[0] + wsum[1] + wsum[2] + wsum[3];
        float cnt = fmaxf((float)(end - beg), 1.0f);
        out[g] = tot / cnt + __ldg(bl);
    }
}

// ---------------------------------------------------------------------------
extern "C" void kernel_launch(void* const* d_in, const int* in_sizes, int n_in,
                              void* d_out, int out_size) {
    const float* x = (const float*)d_in[0];
    const int* ei_raw = (const int*)d_in[1];
    const int* batch_raw = (const int*)d_in[2];
    const float* W1 = (const float*)d_in[3];
    const float* b1 = (const float*)d_in[4];
    const float* W2 = (const float*)d_in[5];
    const float* b2 = (const float*)d_in[6];
    const float* Wl = (const float*)d_in[7];
    const float* bl = (const float*)d_in[8];
    float* out = (float*)d_out;

    static cudaStream_t s1 = nullptr;
    static cudaEvent_t evF = nullptr, evR = nullptr, evJ = nullptr;
    if (!s1) {
        cudaStreamCreate(&s1);
        cudaEventCreateWithFlags(&evF, cudaEventDisableTiming);
        cudaEventCreateWithFlags(&evR, cudaEventDisableTiming);
        cudaEventCreateWithFlags(&evJ, cudaEventDisableTiming);
        cudaFuncSetAttribute(gemm2_hmma_kernel,
                             cudaFuncAttributeMaxDynamicSharedMemorySize, SM_GEMM2);
    }

    void* p_deg = nullptr;
    cudaGetSymbolAddress(&p_deg, g_deg);
    cudaMemsetAsync(p_deg, 0, N_NODES * sizeof(int));

    // Fork: side stream converts weights and x (no deps)
    cudaEventRecord(evF, 0);
    cudaStreamWaitEvent(s1, evF, 0);
    w1cvt_kernel<<<1, 256, 0, s1>>>(W1);
    w2cvt_kernel<<<8, 256, 0, s1>>>(W2);
    xcvt_kernel<<<(N_NODES * 2 + 255) / 256, 256, 0, s1>>>(x);

    // Main: degree -> scan (rowstart also produces dinv and seeds cursor)
    deg_kernel<<<(N_EDGES + 255) / 256, 256>>>(ei_raw);
    blocksum_kernel<<<NB, SCAN_B>>>();
    rowstart_kernel<<<NB, SCAN_B>>>();
    cudaEventRecord(evR, 0);

    // Side: gemm1 (needs dinv + xb + w1tb) overlapped with bin on main
    cudaStreamWaitEvent(s1, evR, 0);
    gemm1_hmma_kernel<<<N_TILES, 256, 0, s1>>>();
    cudaEventRecord(evJ, s1);

    bin_kernel<<<(N_EDGES + 255) / 256, 256>>>(ei_raw);

    // Join, then the serial back half (gather/gemm2 are both LTS-bound:
    // overlapping them measured SLOWER — keep serial).
    cudaStreamWaitEvent(0, evJ, 0);
    gather_kernel<<<(N_NODES + 7) / 8, 256>>>(b1, 0);
    gemm2_hmma_kernel<<<N_TILES, 256, SM_GEMM2>>>();
    gather_kernel<<<(N_NODES + 7) / 8, 256>>>(b2, 1);
    pool_head_kernel<<<N_GRAPHS, 128>>>(batch_raw, ei_raw, Wl, bl, out);
}

// round 16
// speedup vs baseline: 1.0922x; 1.0192x over previous
#include <cuda_runtime.h>
#include <cuda_bf16.h>
#include <cstdint>

#define N_NODES 100000
#define N_EDGES 1600000
#define N_FEAT  16
#define HIDDEN  128
#define N_GRAPHS 512
#define HU2 (HIDDEN / 4)
#define SCAN_B 1024
#define NB ((N_NODES + SCAN_B - 1) / SCAN_B)   // 98
#define TILE_M 128
#define N_TILES ((N_NODES + TILE_M - 1) / TILE_M)  // 782
#define PITCH 272                 // smem row pitch (bytes): conflict-free frag loads
#define SM_GEMM2 (2 * 128 * PITCH)  // 69632 dynamic smem

// ---- scratch ----
__device__ uint4  g_hb[N_NODES * 16];     // h*dinv bf16; layer1 then layer2 (serial-safe reuse)
__device__ uint4  g_outb[N_NODES * 16];   // relu(out+b), bf16 (gather out / gemm2 A / pool in)
__device__ uint4  g_xb[N_NODES * 2];      // x as bf16 rows (16 bf16 = 32B per node)
__device__ uint4  g_w2tb[128 * 16];       // W2^T as bf16 [n][k]
__device__ uint4  g_w1tb[128 * 2];        // W1^T as bf16 [n][k], k=16
__device__ float  g_dinv[N_NODES];
__device__ int    g_deg[N_NODES];
__device__ int    g_cursor[N_NODES];      // seeded with row_start by rowstart_kernel
__device__ int    g_row_start[N_NODES + 1];
__device__ int    g_blocksum[NB];
__device__ int    g_csr_src[N_EDGES];

__device__ __forceinline__ int idx_at(const int* __restrict__ p, int i, int is64) {
    return is64 ? p[2 * i] : p[i];
}

// Lane-parallel dtype detect: indices < 2^31, random — if int64, odd words all 0.
__device__ __forceinline__ int detect64(const int* __restrict__ p) {
    int lane = threadIdx.x & 31;
    int z = (p[2 * lane + 1] == 0);
    return __all_sync(0xffffffffu, z);
}

__device__ __forceinline__ uint32_t smem_u32(const void* p) {
    uint32_t a;
    asm("{ .reg .u64 t; cvta.to.shared.u64 t, %1; cvt.u32.u64 %0, t; }" : "=r"(a) : "l"(p));
    return a;
}

// ---------------------------------------------------------------------------
// x (fp32) -> g_xb (bf16). 8 values per thread. No dependencies.
__global__ void xcvt_kernel(const float* __restrict__ x) {
    int t = blockIdx.x * 256 + threadIdx.x;
    if (t >= N_NODES * 2) return;
    float4 lo4 = __ldg((const float4*)x + t * 2);
    float4 hi4 = __ldg((const float4*)x + t * 2 + 1);
    uint4 u;
    asm("cvt.rn.bf16x2.f32 %0, %1, %2;" : "=r"(u.x) : "f"(lo4.y), "f"(lo4.x));
    asm("cvt.rn.bf16x2.f32 %0, %1, %2;" : "=r"(u.y) : "f"(lo4.w), "f"(lo4.z));
    asm("cvt.rn.bf16x2.f32 %0, %1, %2;" : "=r"(u.z) : "f"(hi4.y), "f"(hi4.x));
    asm("cvt.rn.bf16x2.f32 %0, %1, %2;" : "=r"(u.w) : "f"(hi4.w), "f"(hi4.z));
    g_xb[t] = u;
}

// W1 -> w1tb[n][k] bf16 (transposed). 256 threads: n = t>>1, 8-k chunk = t&1.
__global__ void w1cvt_kernel(const float* __restrict__ W1) {
    int t = threadIdx.x;
    if (t >= 256) return;
    int n = t >> 1, ch = t & 1;
    int k0 = ch * 8;
    uint32_t w[4];
#pragma unroll
    for (int j = 0; j < 4; j++) {
        float lo = W1[(k0 + 2 * j) * HIDDEN + n];
        float hi = W1[(k0 + 2 * j + 1) * HIDDEN + n];
        asm("cvt.rn.bf16x2.f32 %0, %1, %2;" : "=r"(w[j]) : "f"(hi), "f"(lo));
    }
    g_w1tb[t] = make_uint4(w[0], w[1], w[2], w[3]);
}

// W2 -> w2tb[n][k] bf16 (transposed)
__global__ void w2cvt_kernel(const float* __restrict__ W2) {
    int t = blockIdx.x * 256 + threadIdx.x;
    if (t >= 128 * 16) return;
    int n = t >> 4, ch = t & 15;
    int k0 = ch * 8;
    uint32_t w[4];
#pragma unroll
    for (int j = 0; j < 4; j++) {
        float lo = W2[(k0 + 2 * j) * HIDDEN + n];
        float hi = W2[(k0 + 2 * j + 1) * HIDDEN + n];
        asm("cvt.rn.bf16x2.f32 %0, %1, %2;" : "=r"(w[j]) : "f"(hi), "f"(lo));
    }
    g_w2tb[t] = make_uint4(w[0], w[1], w[2], w[3]);
}

// Degree histogram: 2 edges/thread, fully coalesced index loads.
__global__ void deg_kernel(const int* __restrict__ ei_raw) {
    int is64 = detect64(ei_raw);
    int t = blockIdx.x * blockDim.x + threadIdx.x;
    if (2 * t >= N_EDGES) return;
    int d0, d1;
    if (is64) {
        int4 v = __ldg((const int4*)(ei_raw + 2 * N_EDGES) + t);   // 2 packed int64
        d0 = v.x; d1 = v.z;
    } else {
        int2 v = __ldg((const int2*)(ei_raw + N_EDGES) + t);
        d0 = v.x; d1 = v.y;
    }
    atomicAdd(&g_deg[d0], 1);
    if (2 * t + 1 < N_EDGES) atomicAdd(&g_deg[d1], 1);
}

__global__ void blocksum_kernel() {
    __shared__ int wsum[32];
    int b = blockIdx.x, tid = threadIdx.x;
    int i = b * SCAN_B + tid;
    int v = (i < N_NODES) ? g_deg[i] : 0;
#pragma unroll
    for (int off = 16; off; off >>= 1) v += __shfl_down_sync(0xffffffffu, v, off);
    if ((tid & 31) == 0) wsum[tid >> 5] = v;
    __syncthreads();
    if (tid < 32) {
        int s = (tid < SCAN_B / 32) ? wsum[tid] : 0;
#pragma unroll
        for (int off = 16; off; off >>= 1) s += __shfl_down_sync(0xffffffffu, s, off);
        if (tid == 0) g_blocksum[b] = s;
    }
}

// rowstart: hierarchical shfl scan + inline blocksum prefix + dinv (fused).
// Also seeds g_cursor = row_start so bin_kernel skips the row_start read.
__global__ void rowstart_kernel() {
    __shared__ int wsum[32];
    __shared__ int s_pref;
    int b = blockIdx.x, tid = threadIdx.x;
    int lane = tid & 31, wrp = tid >> 5;

    if (tid < 32) {
        int sum = 0;
        for (int j = tid; j < b; j += 32) sum += g_blocksum[j];
#pragma unroll
        for (int off = 16; off; off >>= 1) sum += __shfl_down_sync(0xffffffffu, sum, off);
        if (tid == 0) s_pref = sum;
    }

    int i = b * SCAN_B + tid;
    int v = (i < N_NODES) ? g_deg[i] : 0;
    if (i < N_NODES) g_dinv[i] = rsqrtf((float)v + 1.0f);
    int sv = v;
#pragma unroll
    for (int off = 1; off < 32; off <<= 1) {
        int t = __shfl_up_sync(0xffffffffu, sv, off);
        if (lane >= off) sv += t;
    }
    if (lane == 31) wsum[wrp] = sv;
    __syncthreads();
    if (wrp == 0) {
        int s = wsum[lane];
#pragma unroll
        for (int off = 1; off < 32; off <<= 1) {
            int t = __shfl_up_sync(0xffffffffu, s, off);
            if (lane >= off) s += t;
        }
        wsum[lane] = s;
    }
    __syncthreads();
    int incl = sv + (wrp ? wsum[wrp - 1] : 0);
    int excl = incl - v + s_pref;
    if (i < N_NODES) {
        g_row_start[i] = excl;
        g_cursor[i] = excl;            // seed bin cursor
    }
    if (i == N_NODES - 1) g_row_start[N_NODES] = excl + v;
}

// bin: cursor pre-seeded; 2 edges/thread, coalesced src+dst loads.
__global__ void bin_kernel(const int* __restrict__ ei_raw) {
    int is64 = detect64(ei_raw);
    int t = blockIdx.x * blockDim.x + threadIdx.x;
    if (2 * t >= N_EDGES) return;
    int s0, s1, d0, d1;
    if (is64) {
        int4 s = __ldg((const int4*)ei_raw + t);
        int4 d = __ldg((const int4*)(ei_raw + 2 * N_EDGES) + t);
        s0 = s.x; s1 = s.z; d0 = d.x; d1 = d.z;
    } else {
        int2 s = __ldg((const int2*)ei_raw + t);
        int2 d = __ldg((const int2*)(ei_raw + N_EDGES) + t);
        s0 = s.x; s1 = s.y; d0 = d.x; d1 = d.y;
    }
    int p0 = atomicAdd(&g_cursor[d0], 1);
    g_csr_src[p0] = s0;
    if (2 * t + 1 < N_EDGES) {
        int p1 = atomicAdd(&g_cursor[d1], 1);
        g_csr_src[p1] = s1;
    }
}

// ---------------------------------------------------------------------------
// Layer 1 GEMM via HMMA, zero smem: g_hb = bf16( (x_bf16 @ W1) * dinv ).
__global__ __launch_bounds__(256) void gemm1_hmma_kernel() {
    int tid = threadIdx.x, wid = tid >> 5, lane = tid & 31;
    int row0 = blockIdx.x * TILE_M;
    int r = lane >> 2;
    int kc = (lane & 3) * 4;

    const uint8_t* w1b = (const uint8_t*)g_w1tb;
    uint32_t b0[16], b1[16];
#pragma unroll
    for (int f = 0; f < 16; f++) {
        const uint8_t* p = w1b + (f * 8 + r) * 32 + kc;
        b0[f] = *(const uint32_t*)p;
        b1[f] = *(const uint32_t*)(p + 16);
    }

    int rlo = row0 + wid * 16 + r;
    int rhi = rlo + 8;
    const uint8_t* xb = (const uint8_t*)g_xb;
    bool vlo = rlo < N_NODES, vhi = rhi < N_NODES;
    uint32_t a0 = vlo ? *(const uint32_t*)(xb + rlo * 32 + kc) : 0u;
    uint32_t a2 = vlo ? *(const uint32_t*)(xb + rlo * 32 + kc + 16) : 0u;
    uint32_t a1 = vhi ? *(const uint32_t*)(xb + rhi * 32 + kc) : 0u;
    uint32_t a3 = vhi ? *(const uint32_t*)(xb + rhi * 32 + kc + 16) : 0u;

    float dlo = vlo ? g_dinv[rlo] : 0.f;
    float dhi = vhi ? g_dinv[rhi] : 0.f;
    uint32_t* ghw = (uint32_t*)g_hb;
    int wcol = lane & 3;

#pragma unroll
    for (int f = 0; f < 16; f++) {
        float c0 = 0.f, c1 = 0.f, c2 = 0.f, c3 = 0.f;
        asm volatile(
            "mma.sync.aligned.m16n8k16.row.col.f32.bf16.bf16.f32 "
            "{%0,%1,%2,%3},{%4,%5,%6,%7},{%8,%9},{%0,%1,%2,%3};"
            : "+f"(c0), "+f"(c1), "+f"(c2), "+f"(c3)
            : "r"(a0), "r"(a1), "r"(a2), "r"(a3), "r"(b0[f]), "r"(b1[f]));
        uint32_t plo, phi;
        asm("cvt.rn.bf16x2.f32 %0, %1, %2;" : "=r"(plo) : "f"(c1 * dlo), "f"(c0 * dlo));
        asm("cvt.rn.bf16x2.f32 %0, %1, %2;" : "=r"(phi) : "f"(c3 * dhi), "f"(c2 * dhi));
        if (vlo) ghw[rlo * 64 + f * 4 + wcol] = plo;
        if (vhi) ghw[rhi * 64 + f * 4 + wcol] = phi;
    }
}

// ---------------------------------------------------------------------------
// CSR gather: g_outb = bf16(relu( dinv[d]*(h_pre[d] + Σ_s h_pre[s]) + bias ))
// Reads g_hb (single buffer: serial schedule makes reuse safe across layers).
__global__ void gather_kernel(const float* __restrict__ bias) {
    const uint4* __restrict__ hb = g_hb;
    int w = (blockIdx.x * blockDim.x + threadIdx.x) >> 5;
    int lane = threadIdx.x & 31;
    if (w >= N_NODES) return;

    int beg = g_row_start[w];
    int end = g_row_start[w + 1];
    int half = lane >> 4;
    int l16 = lane & 15;

    float a0 = 0.f, a1 = 0.f, a2 = 0.f, a3 = 0.f;
    float a4 = 0.f, a5 = 0.f, a6 = 0.f, a7 = 0.f;

    int i = beg;
    for (; i + 1 < end; i += 2) {
        int s = g_csr_src[i + half];
        uint4 v = hb[s * 16 + l16];
        float2 f0 = __bfloat1622float2(*(__nv_bfloat162*)&v.x);
        float2 f1 = __bfloat1622float2(*(__nv_bfloat162*)&v.y);
        float2 f2 = __bfloat1622float2(*(__nv_bfloat162*)&v.z);
        float2 f3 = __bfloat1622float2(*(__nv_bfloat162*)&v.w);
        a0 += f0.x; a1 += f0.y; a2 += f1.x; a3 += f1.y;
        a4 += f2.x; a5 += f2.y; a6 += f3.x; a7 += f3.y;
    }
    if (i < end && half == 0) {
        int s = g_csr_src[i];
        uint4 v = hb[s * 16 + l16];
        float2 f0 = __bfloat1622float2(*(__nv_bfloat162*)&v.x);
        float2 f1 = __bfloat1622float2(*(__nv_bfloat162*)&v.y);
        float2 f2 = __bfloat1622float2(*(__nv_bfloat162*)&v.z);
        float2 f3 = __bfloat1622float2(*(__nv_bfloat162*)&v.w);
        a0 += f0.x; a1 += f0.y; a2 += f1.x; a3 += f1.y;
        a4 += f2.x; a5 += f2.y; a6 += f3.x; a7 += f3.y;
    }

    a0 += __shfl_xor_sync(0xffffffffu, a0, 16);
    a1 += __shfl_xor_sync(0xffffffffu, a1, 16);
    a2 += __shfl_xor_sync(0xffffffffu, a2, 16);
    a3 += __shfl_xor_sync(0xffffffffu, a3, 16);
    a4 += __shfl_xor_sync(0xffffffffu, a4, 16);
    a5 += __shfl_xor_sync(0xffffffffu, a5, 16);
    a6 += __shfl_xor_sync(0xffffffffu, a6, 16);
    a7 += __shfl_xor_sync(0xffffffffu, a7, 16);

    if (half == 0) {
        uint4 v = hb[w * 16 + l16];
        float2 f0 = __bfloat1622float2(*(__nv_bfloat162*)&v.x);
        float2 f1 = __bfloat1622float2(*(__nv_bfloat162*)&v.y);
        float2 f2 = __bfloat1622float2(*(__nv_bfloat162*)&v.z);
        float2 f3 = __bfloat1622float2(*(__nv_bfloat162*)&v.w);
        a0 += f0.x; a1 += f0.y; a2 += f1.x; a3 += f1.y;
        a4 += f2.x; a5 += f2.y; a6 += f3.x; a7 += f3.y;

        float invd = g_dinv[w];
        float4 b0 = ((const float4*)bias)[l16 * 2];
        float4 b1 = ((const float4*)bias)[l16 * 2 + 1];
        float v0 = fmaxf(a0 * invd + b0.x, 0.f);
        float v1 = fmaxf(a1 * invd + b0.y, 0.f);
        float v2 = fmaxf(a2 * invd + b0.z, 0.f);
        float v3 = fmaxf(a3 * invd + b0.w, 0.f);
        float v4 = fmaxf(a4 * invd + b1.x, 0.f);
        float v5 = fmaxf(a5 * invd + b1.y, 0.f);
        float v6 = fmaxf(a6 * invd + b1.z, 0.f);
        float v7 = fmaxf(a7 * invd + b1.w, 0.f);
        uint4 o;
        asm("cvt.rn.bf16x2.f32 %0, %1, %2;" : "=r"(o.x) : "f"(v1), "f"(v0));
        asm("cvt.rn.bf16x2.f32 %0, %1, %2;" : "=r"(o.y) : "f"(v3), "f"(v2));
        asm("cvt.rn.bf16x2.f32 %0, %1, %2;" : "=r"(o.z) : "f"(v5), "f"(v4));
        asm("cvt.rn.bf16x2.f32 %0, %1, %2;" : "=r"(o.w) : "f"(v7), "f"(v6));
        g_outb[w * 16 + l16] = o;
    }
}

// ---------------------------------------------------------------------------
// Layer 2 GEMM via mma.sync (HMMA): g_hb = bf16((g_outb @ W2) * dinv)
// (writes back into g_hb — safe: gather1 completed before this launches)
__global__ __launch_bounds__(256) void gemm2_hmma_kernel() {
    extern __shared__ __align__(16) uint8_t smem[];
    uint8_t* sA = smem;
    uint8_t* sB = smem + 128 * PITCH;

    int tid = threadIdx.x, wid = tid >> 5, lane = tid & 31;
    int row0 = blockIdx.x * TILE_M;

    const uint4 zero4 = make_uint4(0, 0, 0, 0);
    for (int g = tid; g < 2048; g += 256) {
        int row = g >> 4, ch = g & 15;
        uint4 va = (row0 + row < N_NODES) ? g_outb[(row0 + row) * 16 + ch] : zero4;
        *(uint4*)(sA + row * PITCH + ch * 16) = va;
        *(uint4*)(sB + row * PITCH + ch * 16) = g_w2tb[g];
    }
    __syncthreads();

    float acc[16][4];
#pragma unroll
    for (int f = 0; f < 16; f++)
#pragma unroll
        for (int j = 0; j < 4; j++) acc[f][j] = 0.f;

    int r = lane >> 2;
    int kc2 = (lane & 3) * 4;
    uint32_t aAddr = smem_u32(sA) + (wid * 16 + r) * PITCH + kc2;
    uint32_t bAddr = smem_u32(sB) + r * PITCH + kc2;

#pragma unroll
    for (int ks = 0; ks < 8; ks++) {
        uint32_t a0, a1, a2, a3;
        uint32_t ka = aAddr + ks * 32;
        asm volatile("ld.shared.b32 %0,[%1];" : "=r"(a0) : "r"(ka));
        asm volatile("ld.shared.b32 %0,[%1];" : "=r"(a1) : "r"(ka + 8 * PITCH));
        asm volatile("ld.shared.b32 %0,[%1];" : "=r"(a2) : "r"(ka + 16));
        asm volatile("ld.shared.b32 %0,[%1];" : "=r"(a3) : "r"(ka + 8 * PITCH + 16));
#pragma unroll
        for (int f = 0; f < 16; f++) {
            uint32_t b0, b1;
            uint32_t kb = bAddr + ks * 32 + f * 8 * PITCH;
            asm volatile("ld.shared.b32 %0,[%1];" : "=r"(b0) : "r"(kb));
            asm volatile("ld.shared.b32 %0,[%1];" : "=r"(b1) : "r"(kb + 16));
            asm volatile(
                "mma.sync.aligned.m16n8k16.row.col.f32.bf16.bf16.f32 "
                "{%0,%1,%2,%3},{%4,%5,%6,%7},{%8,%9},{%0,%1,%2,%3};"
                : "+f"(acc[f][0]), "+f"(acc[f][1]), "+f"(acc[f][2]), "+f"(acc[f][3])
                : "r"(a0), "r"(a1), "r"(a2), "r"(a3), "r"(b0), "r"(b1));
        }
    }

    int rlo = row0 + wid * 16 + r;
    int rhi = rlo + 8;
    float dlo = (rlo < N_NODES) ? g_dinv[rlo] : 0.f;
    float dhi = (rhi < N_NODES) ? g_dinv[rhi] : 0.f;
    uint32_t* ghw = (uint32_t*)g_hb;
    int wcol = (lane & 3);
#pragma unroll
    for (int f = 0; f < 16; f++) {
        uint32_t plo, phi;
        asm("cvt.rn.bf16x2.f32 %0, %1, %2;" : "=r"(plo)
            : "f"(acc[f][1] * dlo), "f"(acc[f][0] * dlo));
        asm("cvt.rn.bf16x2.f32 %0, %1, %2;" : "=r"(phi)
            : "f"(acc[f][3] * dhi), "f"(acc[f][2] * dhi));
        if (rlo < N_NODES) ghw[rlo * 64 + f * 4 + wcol] = plo;
        if (rhi < N_NODES) ghw[rhi * 64 + f * 4 + wcol] = phi;
    }
}

// ---------------------------------------------------------------------------
// Pool + head fused: block per graph (batch sorted). Input g_outb (bf16).
__global__ void pool_head_kernel(const int* __restrict__ batch_raw,
                                 const int* __restrict__ ei_raw,
                                 const float* __restrict__ Wl,
                                 const float* __restrict__ bl,
                                 float* __restrict__ out) {
    int g = blockIdx.x;
    int tid = threadIdx.x;
    int is64 = detect64(ei_raw);

    int lo = 0, hi = N_NODES;
    while (lo < hi) {
        int mid = (lo + hi) >> 1;
        if (idx_at(batch_raw, mid, is64) < g) lo = mid + 1; else hi = mid;
    }
    int beg = lo;
    hi = N_NODES;
    while (lo < hi) {
        int mid = (lo + hi) >> 1;
        if (idx_at(batch_raw, mid, is64) < g + 1) lo = mid + 1; else hi = mid;
    }
    int end = lo;

    const __nv_bfloat16* outb = (const __nv_bfloat16*)g_outb;
    float acc = 0.f;
    for (int n = beg; n < end; n++)
        acc += __bfloat162float(outb[n * HIDDEN + tid]);

    float v = acc * __ldg(Wl + tid);
    __shared__ float wsum[4];
#pragma unroll
    for (int off = 16; off; off >>= 1) v += __shfl_down_sync(0xffffffffu, v, off);
    if ((tid & 31) == 0) wsum[tid >> 5] = v;
    __syncthreads();
    if (tid == 0) {
        float tot = wsum[0] + wsum[1] + wsum[2] + wsum[3];
        float cnt = fmaxf((float)(end - beg), 1.0f);
        out[g] = tot / cnt + __ldg(bl);
    }
}

// ---------------------------------------------------------------------------
extern "C" void kernel_launch(void* const* d_in, const int* in_sizes, int n_in,
                              void* d_out, int out_size) {
    const float* x = (const float*)d_in[0];
    const int* ei_raw = (const int*)d_in[1];
    const int* batch_raw = (const int*)d_in[2];
    const float* W1 = (const float*)d_in[3];
    const float* b1 = (const float*)d_in[4];
    const float* W2 = (const float*)d_in[5];
    const float* b2 = (const float*)d_in[6];
    const float* Wl = (const float*)d_in[7];
    const float* bl = (const float*)d_in[8];
    float* out = (float*)d_out;

    static cudaStream_t s1 = nullptr;
    static cudaEvent_t evF = nullptr, evR = nullptr, evJ = nullptr;
    if (!s1) {
        cudaStreamCreate(&s1);
        cudaEventCreateWithFlags(&evF, cudaEventDisableTiming);
        cudaEventCreateWithFlags(&evR, cudaEventDisableTiming);
        cudaEventCreateWithFlags(&evJ, cudaEventDisableTiming);
        cudaFuncSetAttribute(gemm2_hmma_kernel,
                             cudaFuncAttributeMaxDynamicSharedMemorySize, SM_GEMM2);
    }

    void* p_deg = nullptr;
    cudaGetSymbolAddress(&p_deg, g_deg);
    cudaMemsetAsync(p_deg, 0, N_NODES * sizeof(int));

    // Fork: side stream converts weights and x (no deps)
    cudaEventRecord(evF, 0);
    cudaStreamWaitEvent(s1, evF, 0);
    w1cvt_kernel<<<1, 256, 0, s1>>>(W1);
    w2cvt_kernel<<<8, 256, 0, s1>>>(W2);
    xcvt_kernel<<<(N_NODES * 2 + 255) / 256, 256, 0, s1>>>(x);

    // Main: degree -> scan (rowstart also produces dinv and seeds cursor)
    deg_kernel<<<(N_EDGES / 2 + 255) / 256, 256>>>(ei_raw);
    blocksum_kernel<<<NB, SCAN_B>>>();
    rowstart_kernel<<<NB, SCAN_B>>>();
    cudaEventRecord(evR, 0);

    // Side: gemm1 (needs dinv + xb + w1tb) overlapped with bin on main
    cudaStreamWaitEvent(s1, evR, 0);
    gemm1_hmma_kernel<<<N_TILES, 256, 0, s1>>>();
    cudaEventRecord(evJ, s1);

    bin_kernel<<<(N_EDGES / 2 + 255) / 256, 256>>>(ei_raw);

    // Join, then the serial back half (gather/gemm2 are both LTS-bound:
    // overlapping them measured SLOWER — keep serial).
    cudaStreamWaitEvent(0, evJ, 0);
    gather_kernel<<<(N_NODES + 7) / 8, 256>>>(b1);
    gemm2_hmma_kernel<<<N_TILES, 256, SM_GEMM2>>>();
    gather_kernel<<<(N_NODES + 7) / 8, 256>>>(b2);
    pool_head_kernel<<<N_GRAPHS, 128>>>(batch_raw, ei_raw, Wl, bl, out);
}